// round 5
// baseline (speedup 1.0000x reference)
#include <cuda_runtime.h>
#include <cstdint>

#define BB 16
#define TT 512
#define DD 384
#define OUT_LEN 3584            // T * (MAX_DUR - 1)
#define MAXD 8                  // durations in [0, 8)
#define ROW_BYTES (DD * 4)      // 1536
#define SRC_ROWS 8              // source rows per valid block
#define SRC_BLOCKS (TT / SRC_ROWS)      // 64
#define ZROWS 32                // output rows per pad block
#define ZBLOCKS (OUT_LEN / ZROWS)       // 112
#define NT 128

// One fused kernel:
//   blockIdx.x <  SRC_BLOCKS : source-centric gather/scatter (8 src rows)
//   blockIdx.x >= SRC_BLOCKS : pad zero-fill (32 output rows)
__global__ void __launch_bounds__(NT)
lr_kernel(const float* __restrict__ xs, const int* __restrict__ ds,
          const int* __restrict__ ilens, float* __restrict__ out) {
    __shared__ alignas(128) char buf[SRC_ROWS * ROW_BYTES];   // 12288 B
    __shared__ int csum[TT];
    __shared__ alignas(8) unsigned long long mbar;
    __shared__ int wtot[4];

    const int tid = threadIdx.x;
    const int lane = tid & 31;
    const int w = tid >> 5;
    const int b = blockIdx.y;
    const int bx = blockIdx.x;

    uint32_t mbar_s = (uint32_t)__cvta_generic_to_shared(&mbar);
    uint32_t buf_s  = (uint32_t)__cvta_generic_to_shared(buf);

    if (tid == 0) {
        asm volatile("mbarrier.init.shared::cta.b64 [%0], 1;" :: "r"(mbar_s) : "memory");
        asm volatile("fence.proxy.async.shared::cta;" ::: "memory");
    }

    // ---- masked duration load: 4 consecutive per thread ----
    const int ilen = ilens[b];
    int4 dv = ((const int4*)(ds + b * TT))[tid];
    const int g0 = tid * 4;
    int d0 = (g0 + 0 < ilen) ? dv.x : 0;
    int d1 = (g0 + 1 < ilen) ? dv.y : 0;
    int d2 = (g0 + 2 < ilen) ? dv.z : 0;
    int d3 = (g0 + 3 < ilen) ? dv.w : 0;
    int p1 = d0 + d1, p2 = p1 + d2, p3 = p2 + d3;

    if (bx < SRC_BLOCKS) {
        // ================= source-centric block =================
        // Block-wide inclusive scan -> csum[0..511].
        int x = p3;
        #pragma unroll
        for (int off = 1; off < 32; off <<= 1) {
            int y = __shfl_up_sync(0xFFFFFFFFu, x, off);
            if (lane >= off) x += y;
        }
        if (lane == 31) wtot[w] = x;
        __syncthreads();
        int woff = 0;
        #pragma unroll
        for (int i = 0; i < 4; ++i) woff += (i < w) ? wtot[i] : 0;
        const int excl = woff + x - p3;
        csum[g0 + 0] = excl + d0;
        csum[g0 + 1] = excl + p1;
        csum[g0 + 2] = excl + p2;
        csum[g0 + 3] = excl + p3;
        __syncthreads();   // also orders mbarrier init for warp 0

        const int r0 = bx * SRC_ROWS;

        // Per-row duration / destination start for this block's 8 rows.
        int dr = 0;
        if (tid < SRC_ROWS) {
            int r = r0 + tid;
            int c = csum[r];
            int cp = r ? csum[r - 1] : 0;
            dr = c - cp;
        }
        unsigned ballot = __ballot_sync(0xFFFFFFFFu, (tid < SRC_ROWS) && (dr > 0));
        const int nld = __popc(ballot);

        // TMA loads: one per source row with d>0 (slot = row index).
        if (tid == 0 && nld > 0) {
            asm volatile("mbarrier.arrive.expect_tx.shared::cta.b64 _, [%0], %1;"
                         :: "r"(mbar_s), "r"((uint32_t)(nld * ROW_BYTES)) : "memory");
        }
        __syncwarp();
        if (tid < SRC_ROWS && dr > 0) {
            const char* srcp = (const char*)(xs + (size_t)b * TT * DD)
                             + (size_t)(r0 + tid) * ROW_BYTES;
            asm volatile(
                "cp.async.bulk.shared::cta.global.mbarrier::complete_tx::bytes "
                "[%0], [%1], %2, [%3];"
                :: "r"(buf_s + tid * ROW_BYTES), "l"(srcp),
                   "r"((uint32_t)ROW_BYTES), "r"(mbar_s) : "memory");
        }

        if (tid == 0 && nld > 0) {
            asm volatile(
                "{\n\t"
                ".reg .pred P;\n\t"
                "LRW_%=:\n\t"
                "mbarrier.try_wait.parity.shared::cta.b64 P, [%0], 0;\n\t"
                "@!P bra LRW_%=;\n\t"
                "}"
                :: "r"(mbar_s) : "memory");
        }
        __syncthreads();

        // Stores: thread (src, j) for src in [0,8), j in [0,7) issues one
        // 1536B bulk store of source row src to output row csum[src]-d+j.
        if (tid < SRC_ROWS * (MAXD - 1)) {           // 56 threads
            const int sl = tid / (MAXD - 1);
            const int j  = tid - sl * (MAXD - 1);
            const int r  = r0 + sl;
            const int c  = csum[r];
            const int cp = r ? csum[r - 1] : 0;
            if (j < c - cp) {
                asm volatile("fence.proxy.async.shared::cta;" ::: "memory");
                char* dst = (char*)(out + ((size_t)b * OUT_LEN + (cp + j)) * DD);
                asm volatile(
                    "cp.async.bulk.global.shared::cta.bulk_group [%0], [%1], %2;"
                    :: "l"(dst), "r"(buf_s + sl * ROW_BYTES),
                       "r"((uint32_t)ROW_BYTES) : "memory");
                asm volatile("cp.async.bulk.commit_group;" ::: "memory");
                asm volatile("cp.async.bulk.wait_group.read 0;" ::: "memory");
            }
        }
    } else {
        // ================= pad zero-fill block =================
        // total = sum of masked durations (reduction only).
        int x = p3;
        #pragma unroll
        for (int off = 16; off > 0; off >>= 1)
            x += __shfl_down_sync(0xFFFFFFFFu, x, off);
        if (lane == 0) wtot[w] = x;
        __syncthreads();
        const int total = wtot[0] + wtot[1] + wtot[2] + wtot[3];

        const int r0z = (bx - SRC_BLOCKS) * ZROWS;
        const int pstart = max(total, r0z);
        const int pend = r0z + ZROWS;
        if (pstart < pend) {
            // Zero the smem buffer, then issue <=4 bulk stores from it.
            int4* z = (int4*)buf;
            #pragma unroll
            for (int i = tid; i < SRC_ROWS * ROW_BYTES / 16; i += NT)
                z[i] = make_int4(0, 0, 0, 0);
            __syncthreads();
            if (tid == 0) {
                asm volatile("fence.proxy.async.shared::cta;" ::: "memory");
                #pragma unroll 1
                for (int row = pstart; row < pend; row += SRC_ROWS) {
                    const int nr = min(SRC_ROWS, pend - row);
                    char* dst = (char*)(out + ((size_t)b * OUT_LEN + row) * DD);
                    asm volatile(
                        "cp.async.bulk.global.shared::cta.bulk_group [%0], [%1], %2;"
                        :: "l"(dst), "r"(buf_s),
                           "r"((uint32_t)(nr * ROW_BYTES)) : "memory");
                }
                asm volatile("cp.async.bulk.commit_group;" ::: "memory");
                asm volatile("cp.async.bulk.wait_group.read 0;" ::: "memory");
            }
        }
    }
}

extern "C" void kernel_launch(void* const* d_in, const int* in_sizes, int n_in,
                              void* d_out, int out_size) {
    const float* xs = (const float*)d_in[0];
    const int* ds = (const int*)d_in[1];
    const int* ilens = (const int*)d_in[2];
    float* out = (float*)d_out;

    dim3 grid(SRC_BLOCKS + ZBLOCKS, BB);   // (176, 16)
    lr_kernel<<<grid, NT>>>(xs, ds, ilens, out);
}